// round 6
// baseline (speedup 1.0000x reference)
#include <cuda_runtime.h>
#include <cuda_bf16.h>
#include <cstdint>

// ---------------- problem constants ----------------
#define B_SZ 512
#define D_SZ 256
#define C_SZ 100000
#define C_PAD 100096              // 782 * 128
#define NCHB 782                  // class chunks of 128
#define MARGIN 0.2f
#define SCALE  30.0f
#define SHIFT  30.0f              // fixed LSE shift: logits <= S = 30
#define WNORM_BLOCKS 12500        // 8 classes per block

// GEMM smem: 3 stages x (A 8KB + B 8KB) = 48KB, 3 x 16KB W-fp32 staging, 2KB rbuf
#define STAGE_BYTES 16384
#define WSTG_OFF    49152
#define RBUF_OFF    98304
#define GEMM_SMEM   (98304 + 2048)

// ---------------- device scratch (no runtime alloc) ----------------
__device__ __align__(16) __nv_bfloat16 g_xbf[B_SZ * D_SZ];   // S * l2norm(x), bf16
__device__ float g_winv[C_SZ];                               // 1/max(||w_c||,eps)
__device__ float g_psum[(size_t)B_SZ * NCHB];                // per-(row,chunk) sum exp(v-SHIFT)
__device__ float g_loss[B_SZ];
__device__ unsigned g_cnt;

// ---------------- PTX helpers ----------------
__device__ __forceinline__ uint32_t smem_u32(const void* p) {
    uint32_t a;
    asm("{ .reg .u64 t; cvta.to.shared.u64 t, %1; cvt.u32.u64 %0, t; }" : "=r"(a) : "l"(p));
    return a;
}
#define CP_ASYNC16(dst, src) \
    asm volatile("cp.async.cg.shared.global [%0], [%1], 16;" :: "r"(dst), "l"(src) : "memory")
#define CP_ASYNC16_ZF(dst, src, sz) \
    asm volatile("cp.async.cg.shared.global [%0], [%1], 16, %2;" :: "r"(dst), "l"(src), "r"(sz) : "memory")
#define CP_COMMIT() asm volatile("cp.async.commit_group;" ::: "memory")
#define CP_WAIT(n)  asm volatile("cp.async.wait_group %0;" :: "n"(n) : "memory")

#define LDSM_X4(r0, r1, r2, r3, addr) \
    asm volatile("ldmatrix.sync.aligned.m8n8.x4.shared.b16 {%0,%1,%2,%3}, [%4];" \
        : "=r"(r0), "=r"(r1), "=r"(r2), "=r"(r3) : "r"(addr))

#define MMA_BF16(d0, d1, d2, d3, a0, a1, a2, a3, b0, b1) \
    asm volatile("mma.sync.aligned.m16n8k16.row.col.f32.bf16.bf16.f32 " \
        "{%0,%1,%2,%3}, {%4,%5,%6,%7}, {%8,%9}, {%0,%1,%2,%3};" \
        : "+f"(d0), "+f"(d1), "+f"(d2), "+f"(d3) \
        : "r"(a0), "r"(a1), "r"(a2), "r"(a3), "r"(b0), "r"(b1))

// ---------------- kernel 1: W inverse norms (warms L2 with W) + x -> S*l2norm(x) bf16 ----------------
__global__ void prep_kernel(const float* __restrict__ w, const float* __restrict__ x) {
    if (blockIdx.x < WNORM_BLOCKS) {
        int cls = blockIdx.x * 8 + (threadIdx.x >> 5);
        int lane = threadIdx.x & 31;
        if (cls >= C_SZ) return;
        const float4* wr = (const float4*)(w + (size_t)cls * D_SZ);
        float4 a = wr[lane];
        float4 b = wr[lane + 32];
        float s = a.x*a.x + a.y*a.y + a.z*a.z + a.w*a.w
                + b.x*b.x + b.y*b.y + b.z*b.z + b.w*b.w;
        #pragma unroll
        for (int m = 16; m; m >>= 1) s += __shfl_xor_sync(0xffffffffu, s, m);
        if (lane == 0) g_winv[cls] = 1.0f / fmaxf(sqrtf(s), 1e-12f);
    } else {
        int b = blockIdx.x - WNORM_BLOCKS, t = threadIdx.x;   // 256 threads
        if (b == 0 && t == 0) g_cnt = 0;                      // reset completion counter
        float v = x[b * D_SZ + t];
        float s = v * v;
        #pragma unroll
        for (int m = 16; m; m >>= 1) s += __shfl_xor_sync(0xffffffffu, s, m);
        __shared__ float ws[8];
        if ((t & 31) == 0) ws[t >> 5] = s;
        __syncthreads();
        __shared__ float inv;
        if (t == 0) {
            float tot = 0.f;
            #pragma unroll
            for (int i = 0; i < 8; i++) tot += ws[i];
            inv = 1.0f / fmaxf(sqrtf(tot), 1e-12f);
        }
        __syncthreads();
        g_xbf[b * D_SZ + t] = __float2bfloat16(SCALE * v * inv);
    }
}

// ---------------- kernel 2: bf16 HMMA GEMM with in-kernel W conversion + exp-sum epilogue ----------------
// grid (4, 782). B operand: raw fp32 W staged via cp.async, converted to bf16 in smem;
// winv applied per class in the epilogue. 256 threads = 8 warps (2m x 4n).
__global__ void __launch_bounds__(256, 2)
gemm_lse_kernel(const float* __restrict__ w) {
    extern __shared__ __align__(1024) char smem[];
    const uint32_t sb = smem_u32(smem);
    const int tid = threadIdx.x, lane = tid & 31, wid = tid >> 5;
    const int wm = wid >> 2, wn = wid & 3;            // warp grid 2 x 4
    const int chunk = blockIdx.y, c0 = chunk * 128, b0 = blockIdx.x * 128;

    // ---- A producer indexing (bf16, swizzled 16B chunks) ----
    const int ldRow = tid >> 2, ldC16 = tid & 3;
    const uint32_t swzOff = (uint32_t)ldRow * 64 +
                            ((uint32_t)(ldC16 ^ ((ldRow >> 1) & 3)) << 4);
    const __nv_bfloat16* gA = g_xbf + (size_t)(b0 + ldRow) * D_SZ + ldC16 * 8;

    // ---- W fp32 producer indexing: thread handles 4 float4 chunks per stage ----
    const float* wsrc[4];
    uint32_t wsz[4];
    #pragma unroll
    for (int it = 0; it < 4; it++) {
        int f = tid + it * 256;              // float4 index in 128x32 fp32 tile
        int r = f >> 3;                      // class row 0..127
        wsrc[it] = w + (size_t)(c0 + r) * D_SZ + (f & 7) * 4;
        wsz[it] = (c0 + r < C_SZ) ? 16u : 0u;
    }

    auto load_stage = [&](int kt) {
        int st = kt % 3;
        uint32_t abase = sb + st * STAGE_BYTES;
        uint32_t wstg  = sb + WSTG_OFF + st * STAGE_BYTES;
        const __nv_bfloat16* a = gA + kt * 32;
        CP_ASYNC16(abase + swzOff,        a);
        CP_ASYNC16(abase + swzOff + 4096, a + (size_t)64 * D_SZ);
        #pragma unroll
        for (int it = 0; it < 4; it++) {
            int f = tid + it * 256;
            CP_ASYNC16_ZF(wstg + (uint32_t)f * 16, wsrc[it] + kt * 32, wsz[it]);
        }
        CP_COMMIT();
    };

    // ---- fp32 -> bf16 transform into the swizzled B tile ----
    auto transform = [&](int kt) {
        int st = kt % 3;
        const float4* ws = (const float4*)(smem + WSTG_OFF + st * STAGE_BYTES);
        char* bt = smem + st * STAGE_BYTES + 8192;
        #pragma unroll
        for (int it = 0; it < 4; it++) {
            int f = tid + it * 256;
            float4 v = ws[f];
            int r = f >> 3, c16 = (f >> 1) & 3, half = f & 1;
            __nv_bfloat162 h0 = __floats2bfloat162_rn(v.x, v.y);
            __nv_bfloat162 h1 = __floats2bfloat162_rn(v.z, v.w);
            uint2 pk;
            pk.x = *(uint32_t*)&h0;
            pk.y = *(uint32_t*)&h1;
            *(uint2*)(bt + r * 64 + ((c16 ^ ((r >> 1) & 3)) << 4) + half * 8) = pk;
        }
    };

    // ---- ldmatrix consumer indexing ----
    const int rA = wm * 64 + (lane & 15);
    const uint32_t aoff = (uint32_t)rA * 64;
    const int saN = (rA >> 1) & 3;
    const int cA = lane >> 4;
    const int rB = wn * 32 + ((lane >> 4) << 3) + (lane & 7);
    const uint32_t boff = (uint32_t)rB * 64;
    const int sbN = (rB >> 1) & 3;
    const int cB = (lane >> 3) & 1;

    float acc[4][4][4];
    #pragma unroll
    for (int i = 0; i < 4; i++)
        #pragma unroll
        for (int j = 0; j < 4; j++)
            #pragma unroll
            for (int e = 0; e < 4; e++) acc[i][j][e] = 0.f;

    auto compute_stage = [&](int kt) {
        int st = kt % 3;
        uint32_t aBase = sb + st * STAGE_BYTES;
        uint32_t bBase = aBase + 8192;
        #pragma unroll
        for (int s = 0; s < 2; s++) {                 // two k16 steps per BK=32
            uint32_t a_[4][4], b_[2][4];
            #pragma unroll
            for (int mt = 0; mt < 4; mt++) {
                uint32_t ad = aBase + aoff + mt * 1024 +
                              ((uint32_t)((s * 2 + cA) ^ saN) << 4);
                LDSM_X4(a_[mt][0], a_[mt][1], a_[mt][2], a_[mt][3], ad);
            }
            #pragma unroll
            for (int jp = 0; jp < 2; jp++) {
                uint32_t bd = bBase + boff + jp * 1024 +
                              ((uint32_t)((s * 2 + cB) ^ sbN) << 4);
                LDSM_X4(b_[jp][0], b_[jp][1], b_[jp][2], b_[jp][3], bd);
            }
            #pragma unroll
            for (int mt = 0; mt < 4; mt++)
                #pragma unroll
                for (int nt = 0; nt < 4; nt++) {
                    int jp = nt >> 1, hb = (nt & 1) * 2;
                    MMA_BF16(acc[mt][nt][0], acc[mt][nt][1], acc[mt][nt][2], acc[mt][nt][3],
                             a_[mt][0], a_[mt][1], a_[mt][2], a_[mt][3],
                             b_[jp][hb], b_[jp][hb + 1]);
                }
        }
    };

    // ---- pipeline: 8 K-stages, 3-deep ring, 2 loads in flight ----
    load_stage(0); load_stage(1);
    #pragma unroll 1
    for (int kt = 0; kt < 7; kt++) {
        CP_WAIT(1); __syncthreads();
        transform(kt);
        __syncthreads();
        compute_stage(kt);
        if (kt < 6) load_stage(kt + 2);
    }
    CP_WAIT(0); __syncthreads();
    transform(7);
    __syncthreads();
    compute_stage(7);

    // ---- epilogue: per-row sum of exp(acc * winv - SHIFT) ----
    const bool edge = (c0 + 128 > C_SZ);
    float wv[4][2];
    #pragma unroll
    for (int nt = 0; nt < 4; nt++)
        #pragma unroll
        for (int e = 0; e < 2; e++) {
            int c = c0 + wn * 32 + nt * 8 + (lane & 3) * 2 + e;
            wv[nt][e] = (c < C_SZ) ? g_winv[c] : 0.f;
        }

    float es[4][2];
    #pragma unroll
    for (int mt = 0; mt < 4; mt++) { es[mt][0] = 0.f; es[mt][1] = 0.f; }
    #pragma unroll
    for (int mt = 0; mt < 4; mt++)
        #pragma unroll
        for (int nt = 0; nt < 4; nt++) {
            int cgb = c0 + wn * 32 + nt * 8 + (lane & 3) * 2;
            #pragma unroll
            for (int h = 0; h < 2; h++)
                #pragma unroll
                for (int e = 0; e < 2; e++) {
                    float t = __expf(acc[mt][nt][h * 2 + e] * wv[nt][e] - SHIFT);
                    if (edge && (cgb + e >= C_SZ)) t = 0.f;
                    es[mt][h] += t;
                }
        }
    #pragma unroll
    for (int m = 1; m <= 2; m <<= 1)
        #pragma unroll
        for (int mt = 0; mt < 4; mt++) {
            es[mt][0] += __shfl_xor_sync(0xffffffffu, es[mt][0], m);
            es[mt][1] += __shfl_xor_sync(0xffffffffu, es[mt][1], m);
        }

    float* rbuf = (float*)(smem + RBUF_OFF);
    if ((lane & 3) == 0) {
        int rl = lane >> 2;
        #pragma unroll
        for (int mt = 0; mt < 4; mt++) {
            rbuf[(wm * 4 + wn) * 64 + mt * 16 + rl]     = es[mt][0];
            rbuf[(wm * 4 + wn) * 64 + mt * 16 + 8 + rl] = es[mt][1];
        }
    }
    __syncthreads();
    if (tid < 128) {
        int wmx = tid >> 6, rl = tid & 63;
        float s = rbuf[(wmx * 4 + 0) * 64 + rl] + rbuf[(wmx * 4 + 1) * 64 + rl]
                + rbuf[(wmx * 4 + 2) * 64 + rl] + rbuf[(wmx * 4 + 3) * 64 + rl];
        g_psum[(size_t)(b0 + tid) * NCHB + chunk] = s;
    }
}

// ---------------- kernel 3: per-row specials + LSE merge + loss + fused final ----------------
__global__ void row_kernel(const float* __restrict__ w, const float* __restrict__ lamp,
                           const int* __restrict__ t1, const int* __restrict__ p1,
                           const int* __restrict__ t2, const int* __restrict__ p2,
                           float* __restrict__ out) {
    int b = blockIdx.x;
    int tid = threadIdx.x, wid = tid >> 5, lane = tid & 31;

    __shared__ float sv[4], svraw[4];
    __shared__ int   sidx[4];
    __shared__ float ss[256];
    __shared__ bool  lastb;

    int i0 = t1[b], i1 = p1[b], i2 = t2[b], i3 = p2[b];

    if (wid < 4) {
        int qi = (wid == 0) ? i0 : (wid == 1) ? i1 : (wid == 2) ? i2 : i3;
        // replicate GEMM arithmetic: bf16(x_s) dot bf16(w_raw), fp32 accum, * winv
        const uint4* xr = (const uint4*)(g_xbf + (size_t)b * D_SZ);
        const float4* wr = (const float4*)(w + (size_t)qi * D_SZ);
        uint4 xv = xr[lane];                          // 8 bf16
        float4 w0 = wr[2 * lane], w1 = wr[2 * lane + 1];
        const uint32_t* xu = (const uint32_t*)&xv;
        float wq[8] = {w0.x, w0.y, w0.z, w0.w, w1.x, w1.y, w1.z, w1.w};
        float s = 0.f;
        #pragma unroll
        for (int i = 0; i < 4; i++) {
            float2 xf = __bfloat1622float2(*(const __nv_bfloat162*)&xu[i]);
            float wb0 = __bfloat162float(__float2bfloat16(wq[2 * i]));
            float wb1 = __bfloat162float(__float2bfloat16(wq[2 * i + 1]));
            s += xf.x * wb0 + xf.y * wb1;
        }
        #pragma unroll
        for (int m = 16; m; m >>= 1) s += __shfl_xor_sync(0xffffffffu, s, m);
        if (lane == 0) {
            float raw = s * g_winv[qi];               // S * cos (GEMM-equivalent)
            float val = raw;
            if (qi == i0) val = raw - SCALE * MARGIN; // pre-scale scatter
            if (qi == i1) val = raw / SCALE - MARGIN; // post-scale scatters
            if (qi == i2) val = raw / SCALE - MARGIN;
            if (qi == i3) val = raw / SCALE - MARGIN; // last write wins
            svraw[wid] = raw;
            sv[wid] = val;
            sidx[wid] = qi;
        }
    }

    float s = 0.f;
    for (int i = tid; i < NCHB; i += 256) s += g_psum[(size_t)b * NCHB + i];
    ss[tid] = s;
    __syncthreads();
    for (int st = 128; st; st >>= 1) {
        if (tid < st) ss[tid] += ss[tid + st];
        __syncthreads();
    }

    if (tid == 0) {
        float S0 = ss[0];
        #pragma unroll
        for (int q = 0; q < 3; q++) {
            bool lastq = true;
            #pragma unroll
            for (int r = q + 1; r < 4; r++) if (sidx[r] == sidx[q]) lastq = false;
            if (lastq) S0 += __expf(sv[q] - SHIFT) - __expf(svraw[q] - SHIFT);
        }
        S0 += __expf(sv[3] - SHIFT) - __expf(svraw[3] - SHIFT);
        float lz = SHIFT + logf(S0);
        float lam = *lamp;
        g_loss[b] = lam * (0.2f * (lz - sv[0]) + 0.8f * (lz - sv[1]))
                  + (1.f - lam) * (0.2f * (lz - sv[2]) + 0.8f * (lz - sv[3]));
        __threadfence();
        lastb = (atomicAdd(&g_cnt, 1u) == B_SZ - 1);
    }
    __syncthreads();

    if (lastb) {   // deterministic final reduction by the last-arriving block
        float r = 0.f;
        for (int i = tid; i < B_SZ; i += 256) r += __ldcg(&g_loss[i]);
        ss[tid] = r;
        __syncthreads();
        for (int st = 128; st; st >>= 1) {
            if (tid < st) ss[tid] += ss[tid + st];
            __syncthreads();
        }
        if (tid == 0) out[0] = ss[0] / (float)B_SZ;
    }
}

// ---------------- host launch ----------------
extern "C" void kernel_launch(void* const* d_in, const int* in_sizes, int n_in,
                              void* d_out, int out_size) {
    const float* x   = (const float*)d_in[0];
    const float* w   = (const float*)d_in[1];
    const float* lam = (const float*)d_in[2];
    const int* t1    = (const int*)d_in[3];
    const int* p1    = (const int*)d_in[4];
    const int* t2    = (const int*)d_in[5];
    const int* p2    = (const int*)d_in[6];
    float* out = (float*)d_out;

    static bool attr_set = false;
    if (!attr_set) {
        cudaFuncSetAttribute(gemm_lse_kernel,
                             cudaFuncAttributeMaxDynamicSharedMemorySize, GEMM_SMEM);
        attr_set = true;
    }

    prep_kernel<<<WNORM_BLOCKS + B_SZ, 256>>>(w, x);
    gemm_lse_kernel<<<dim3(4, NCHB), 256, GEMM_SMEM>>>(w);
    row_kernel<<<B_SZ, 256>>>(w, lam, t1, p1, t2, p2, out);
}

// round 7
// speedup vs baseline: 1.1215x; 1.1215x over previous
#include <cuda_runtime.h>
#include <cuda_fp16.h>
#include <cstdint>

// ---------------- problem constants ----------------
#define B_SZ 512
#define D_SZ 256
#define C_SZ 100000
#define C_PAD 100096              // 782 * 128
#define NCHB 782                  // class chunks of 128
#define MARGIN 0.2f
#define SCALE  30.0f
#define SHIFT  30.0f              // fixed LSE shift: logits <= S = 30
#define WCONV_BLOCKS 6250         // 16 classes per block (2 per warp)

// GEMM smem: 4 stages x (A 8KB + B 8KB) = 64KB, + 2KB reduce buffer
#define STAGE_BYTES 16384
#define RBUF_OFF    65536
#define GEMM_SMEM   (65536 + 2048)

// ---------------- device scratch (no runtime alloc) ----------------
__device__ __align__(16) __half g_wh[(size_t)C_PAD * D_SZ];  // l2norm(W) fp16; pad rows zero
__device__ __align__(16) __half g_xh[B_SZ * D_SZ];           // S * l2norm(x) fp16
__device__ float g_psum[(size_t)B_SZ * NCHB];   // per-(row, chunk) sum of exp(v - SHIFT)
__device__ float g_loss[B_SZ];
__device__ unsigned g_cnt;

// ---------------- PTX helpers ----------------
__device__ __forceinline__ uint32_t smem_u32(const void* p) {
    uint32_t a;
    asm("{ .reg .u64 t; cvta.to.shared.u64 t, %1; cvt.u32.u64 %0, t; }" : "=r"(a) : "l"(p));
    return a;
}
#define CP_ASYNC16(dst, src) \
    asm volatile("cp.async.cg.shared.global [%0], [%1], 16;" :: "r"(dst), "l"(src) : "memory")
#define CP_COMMIT() asm volatile("cp.async.commit_group;" ::: "memory")
#define CP_WAIT(n)  asm volatile("cp.async.wait_group %0;" :: "n"(n) : "memory")

#define LDSM_X4(r0, r1, r2, r3, addr) \
    asm volatile("ldmatrix.sync.aligned.m8n8.x4.shared.b16 {%0,%1,%2,%3}, [%4];" \
        : "=r"(r0), "=r"(r1), "=r"(r2), "=r"(r3) : "r"(addr))

// fp16 in, fp16 accumulate: D(2x f16x2) = A(4) * B(2) + D
#define MMA_F16ACC(d0, d1, a0, a1, a2, a3, b0, b1) \
    asm volatile("mma.sync.aligned.m16n8k16.row.col.f16.f16.f16.f16 " \
        "{%0,%1}, {%2,%3,%4,%5}, {%6,%7}, {%0,%1};" \
        : "+r"(d0), "+r"(d1) \
        : "r"(a0), "r"(a1), "r"(a2), "r"(a3), "r"(b0), "r"(b1))

// ---------------- kernel 1: fused prep ----------------
// blocks [0, 6250): W rows -> l2norm fp16 (16 classes/block, 2 per warp, MLP=4)
// blocks [6250, 6762): x row -> S * l2norm(x) fp16
__global__ void prep_kernel(const float* __restrict__ w, const float* __restrict__ x) {
    if (blockIdx.x < WCONV_BLOCKS) {
        int cls0 = blockIdx.x * 16 + (threadIdx.x >> 5) * 2;
        int lane = threadIdx.x & 31;
        const float4* w0r = (const float4*)(w + (size_t)cls0 * D_SZ);
        const float4* w1r = (const float4*)(w + (size_t)(cls0 + 1) * D_SZ);
        float4 a0 = w0r[lane], a1 = w0r[lane + 32];      // class cls0
        float4 b0 = w1r[lane], b1 = w1r[lane + 32];      // class cls0+1
        float sa = a0.x*a0.x + a0.y*a0.y + a0.z*a0.z + a0.w*a0.w
                 + a1.x*a1.x + a1.y*a1.y + a1.z*a1.z + a1.w*a1.w;
        float sb = b0.x*b0.x + b0.y*b0.y + b0.z*b0.z + b0.w*b0.w
                 + b1.x*b1.x + b1.y*b1.y + b1.z*b1.z + b1.w*b1.w;
        #pragma unroll
        for (int m = 16; m; m >>= 1) {
            sa += __shfl_xor_sync(0xffffffffu, sa, m);
            sb += __shfl_xor_sync(0xffffffffu, sb, m);
        }
        float ia = 1.0f / fmaxf(sqrtf(sa), 1e-12f);
        float ib = 1.0f / fmaxf(sqrtf(sb), 1e-12f);
        __half2* o0 = (__half2*)(g_wh + (size_t)cls0 * D_SZ);
        __half2* o1 = (__half2*)(g_wh + (size_t)(cls0 + 1) * D_SZ);
        o0[2*lane]        = __floats2half2_rn(a0.x * ia, a0.y * ia);
        o0[2*lane + 1]    = __floats2half2_rn(a0.z * ia, a0.w * ia);
        o0[64 + 2*lane]   = __floats2half2_rn(a1.x * ia, a1.y * ia);
        o0[64 + 2*lane+1] = __floats2half2_rn(a1.z * ia, a1.w * ia);
        o1[2*lane]        = __floats2half2_rn(b0.x * ib, b0.y * ib);
        o1[2*lane + 1]    = __floats2half2_rn(b0.z * ib, b0.w * ib);
        o1[64 + 2*lane]   = __floats2half2_rn(b1.x * ib, b1.y * ib);
        o1[64 + 2*lane+1] = __floats2half2_rn(b1.z * ib, b1.w * ib);
    } else {
        int b = blockIdx.x - WCONV_BLOCKS, t = threadIdx.x;   // 256 threads
        if (b == 0 && t == 0) g_cnt = 0;                      // reset completion counter
        float v = x[b * D_SZ + t];
        float s = v * v;
        #pragma unroll
        for (int m = 16; m; m >>= 1) s += __shfl_xor_sync(0xffffffffu, s, m);
        __shared__ float ws[8];
        if ((t & 31) == 0) ws[t >> 5] = s;
        __syncthreads();
        __shared__ float inv;
        if (t == 0) {
            float tot = 0.f;
            #pragma unroll
            for (int i = 0; i < 8; i++) tot += ws[i];
            inv = 1.0f / fmaxf(sqrtf(tot), 1e-12f);
        }
        __syncthreads();
        g_xh[b * D_SZ + t] = __float2half_rn(SCALE * v * inv);
    }
}

// ---------------- kernel 2: fp16 HMMA (f16 accum) GEMM + exp-sum epilogue ----------------
// grid (4, 782). 256 threads = 8 warps (2m x 4n), warp tile 64m x 32n, k16 steps.
__global__ void __launch_bounds__(256, 2)
gemm_lse_kernel() {
    extern __shared__ __align__(1024) char smem[];
    const uint32_t sb = smem_u32(smem);
    const int tid = threadIdx.x, lane = tid & 31, wid = tid >> 5;
    const int wm = wid >> 2, wn = wid & 3;            // warp grid 2 x 4
    const int chunk = blockIdx.y, c0 = chunk * 128, b0 = blockIdx.x * 128;

    // ---- cp.async producer indexing (swizzled 16B chunks) ----
    const int ldRow = tid >> 2, ldC16 = tid & 3;
    const uint32_t swzOff = (uint32_t)ldRow * 64 +
                            ((uint32_t)(ldC16 ^ ((ldRow >> 1) & 3)) << 4);
    const __half* gA = g_xh + (size_t)(b0 + ldRow) * D_SZ + ldC16 * 8;
    const __half* gB = g_wh + (size_t)(c0 + ldRow) * D_SZ + ldC16 * 8;

    auto load_stage = [&](int kt) {
        uint32_t abase = sb + (kt & 3) * STAGE_BYTES;
        uint32_t bbase = abase + 8192;
        const __half* a = gA + kt * 32;
        const __half* b = gB + kt * 32;
        CP_ASYNC16(abase + swzOff,        a);
        CP_ASYNC16(abase + swzOff + 4096, a + (size_t)64 * D_SZ);
        CP_ASYNC16(bbase + swzOff,        b);
        CP_ASYNC16(bbase + swzOff + 4096, b + (size_t)64 * D_SZ);
        CP_COMMIT();
    };

    // ---- ldmatrix consumer indexing ----
    const int rA = wm * 64 + (lane & 15);
    const uint32_t aoff = (uint32_t)rA * 64;
    const int saN = (rA >> 1) & 3;
    const int cA = lane >> 4;
    const int rB = wn * 32 + ((lane >> 4) << 3) + (lane & 7);
    const uint32_t boff = (uint32_t)rB * 64;
    const int sbN = (rB >> 1) & 3;
    const int cB = (lane >> 3) & 1;

    uint32_t acc[4][4][2];                 // f16x2 accumulators
    #pragma unroll
    for (int i = 0; i < 4; i++)
        #pragma unroll
        for (int j = 0; j < 4; j++) { acc[i][j][0] = 0u; acc[i][j][1] = 0u; }

    auto compute_stage = [&](int st) {
        uint32_t aBase = sb + st * STAGE_BYTES;
        uint32_t bBase = aBase + 8192;
        #pragma unroll
        for (int s = 0; s < 2; s++) {                 // two k16 steps per BK=32
            uint32_t a_[4][4], b_[2][4];
            #pragma unroll
            for (int mt = 0; mt < 4; mt++) {
                uint32_t ad = aBase + aoff + mt * 1024 +
                              ((uint32_t)((s * 2 + cA) ^ saN) << 4);
                LDSM_X4(a_[mt][0], a_[mt][1], a_[mt][2], a_[mt][3], ad);
            }
            #pragma unroll
            for (int jp = 0; jp < 2; jp++) {
                uint32_t bd = bBase + boff + jp * 1024 +
                              ((uint32_t)((s * 2 + cB) ^ sbN) << 4);
                LDSM_X4(b_[jp][0], b_[jp][1], b_[jp][2], b_[jp][3], bd);
            }
            #pragma unroll
            for (int mt = 0; mt < 4; mt++)
                #pragma unroll
                for (int nt = 0; nt < 4; nt++) {
                    int jp = nt >> 1, hb = (nt & 1) * 2;
                    MMA_F16ACC(acc[mt][nt][0], acc[mt][nt][1],
                               a_[mt][0], a_[mt][1], a_[mt][2], a_[mt][3],
                               b_[jp][hb], b_[jp][hb + 1]);
                }
        }
    };

    // ---- pipeline: 8 K-stages, 4 buffers, 3 in flight ----
    load_stage(0); load_stage(1); load_stage(2);
    #pragma unroll 1
    for (int kt = 0; kt < 5; kt++) {
        CP_WAIT(2); __syncthreads();
        compute_stage(kt & 3);
        load_stage(kt + 3);
    }
    CP_WAIT(2); __syncthreads(); compute_stage(1);
    CP_WAIT(1); __syncthreads(); compute_stage(2);
    CP_WAIT(0); __syncthreads(); compute_stage(3);

    // ---- epilogue: per-row sum of exp(v - SHIFT) ----
    const bool edge = (c0 + 128 > C_SZ);
    float es[4][2];
    #pragma unroll
    for (int mt = 0; mt < 4; mt++) { es[mt][0] = 0.f; es[mt][1] = 0.f; }
    #pragma unroll
    for (int mt = 0; mt < 4; mt++)
        #pragma unroll
        for (int nt = 0; nt < 4; nt++) {
            int cgb = c0 + wn * 32 + nt * 8 + (lane & 3) * 2;
            #pragma unroll
            for (int h = 0; h < 2; h++) {
                float2 v = __half22float2(*(__half2*)&acc[mt][nt][h]);
                float t0 = __expf(v.x - SHIFT);
                float t1 = __expf(v.y - SHIFT);
                if (edge && (cgb + 0 >= C_SZ)) t0 = 0.f;
                if (edge && (cgb + 1 >= C_SZ)) t1 = 0.f;
                es[mt][h] += t0 + t1;
            }
        }
    #pragma unroll
    for (int m = 1; m <= 2; m <<= 1)
        #pragma unroll
        for (int mt = 0; mt < 4; mt++) {
            es[mt][0] += __shfl_xor_sync(0xffffffffu, es[mt][0], m);
            es[mt][1] += __shfl_xor_sync(0xffffffffu, es[mt][1], m);
        }

    float* rbuf = (float*)(smem + RBUF_OFF);          // disjoint from stage buffers
    if ((lane & 3) == 0) {
        int rl = lane >> 2;
        #pragma unroll
        for (int mt = 0; mt < 4; mt++) {
            rbuf[(wm * 4 + wn) * 64 + mt * 16 + rl]     = es[mt][0];
            rbuf[(wm * 4 + wn) * 64 + mt * 16 + 8 + rl] = es[mt][1];
        }
    }
    __syncthreads();
    if (tid < 128) {
        int wmx = tid >> 6, rl = tid & 63;
        float s = rbuf[(wmx * 4 + 0) * 64 + rl] + rbuf[(wmx * 4 + 1) * 64 + rl]
                + rbuf[(wmx * 4 + 2) * 64 + rl] + rbuf[(wmx * 4 + 3) * 64 + rl];
        g_psum[(size_t)(b0 + tid) * NCHB + chunk] = s;
    }
}

// ---------------- kernel 3: per-row specials + LSE merge + loss + fused final ----------------
__global__ void row_kernel(const float* __restrict__ lamp,
                           const int* __restrict__ t1, const int* __restrict__ p1,
                           const int* __restrict__ t2, const int* __restrict__ p2,
                           float* __restrict__ out) {
    int b = blockIdx.x;
    int tid = threadIdx.x, wid = tid >> 5, lane = tid & 31;

    __shared__ float sv[4], svraw[4];
    __shared__ int   sidx[4];
    __shared__ float ss[256];
    __shared__ bool  lastb;

    int i0 = t1[b], i1 = p1[b], i2 = t2[b], i3 = p2[b];

    if (wid < 4) {
        int qi = (wid == 0) ? i0 : (wid == 1) ? i1 : (wid == 2) ? i2 : i3;
        const uint4* xr = (const uint4*)(g_xh + (size_t)b * D_SZ);
        const uint4* wr = (const uint4*)(g_wh + (size_t)qi * D_SZ);
        uint4 xv = xr[lane], wv = wr[lane];   // 8 fp16 each
        float s = 0.f;
        const uint32_t* xu = (const uint32_t*)&xv;
        const uint32_t* wu = (const uint32_t*)&wv;
        #pragma unroll
        for (int i = 0; i < 4; i++) {
            float2 xf = __half22float2(*(const __half2*)&xu[i]);
            float2 wf = __half22float2(*(const __half2*)&wu[i]);
            s += xf.x * wf.x + xf.y * wf.y;
        }
        #pragma unroll
        for (int m = 16; m; m >>= 1) s += __shfl_xor_sync(0xffffffffu, s, m);
        if (lane == 0) {
            float raw = s;                               // ~= what the GEMM summed
            float val = raw;
            if (qi == i0) val = raw - SCALE * MARGIN;    // pre-scale scatter
            if (qi == i1) val = raw / SCALE - MARGIN;    // post-scale scatters
            if (qi == i2) val = raw / SCALE - MARGIN;
            if (qi == i3) val = raw / SCALE - MARGIN;    // last write wins
            svraw[wid] = raw;
            sv[wid] = val;
            sidx[wid] = qi;
        }
    }

    float s = 0.f;
    for (int i = tid; i < NCHB; i += 256) s += g_psum[(size_t)b * NCHB + i];
    ss[tid] = s;
    __syncthreads();
    for (int st = 128; st; st >>= 1) {
        if (tid < st) ss[tid] += ss[tid + st];
        __syncthreads();
    }

    if (tid == 0) {
        float S0 = ss[0];
        #pragma unroll
        for (int q = 0; q < 3; q++) {
            bool lastq = true;
            #pragma unroll
            for (int r = q + 1; r < 4; r++) if (sidx[r] == sidx[q]) lastq = false;
            if (lastq) S0 += __expf(sv[q] - SHIFT) - __expf(svraw[q] - SHIFT);
        }
        S0 += __expf(sv[3] - SHIFT) - __expf(svraw[3] - SHIFT);
        float lz = SHIFT + logf(S0);
        float lam = *lamp;
        g_loss[b] = lam * (0.2f * (lz - sv[0]) + 0.8f * (lz - sv[1]))
                  + (1.f - lam) * (0.2f * (lz - sv[2]) + 0.8f * (lz - sv[3]));
        __threadfence();
        lastb = (atomicAdd(&g_cnt, 1u) == B_SZ - 1);
    }
    __syncthreads();

    if (lastb) {   // deterministic final reduction by the last-arriving block
        float r = 0.f;
        for (int i = tid; i < B_SZ; i += 256) r += __ldcg(&g_loss[i]);
        ss[tid] = r;
        __syncthreads();
        for (int st = 128; st; st >>= 1) {
            if (tid < st) ss[tid] += ss[tid + st];
            __syncthreads();
        }
        if (tid == 0) out[0] = ss[0] / (float)B_SZ;
    }
}

// ---------------- host launch ----------------
extern "C" void kernel_launch(void* const* d_in, const int* in_sizes, int n_in,
                              void* d_out, int out_size) {
    const float* x   = (const float*)d_in[0];
    const float* w   = (const float*)d_in[1];
    const float* lam = (const float*)d_in[2];
    const int* t1    = (const int*)d_in[3];
    const int* p1    = (const int*)d_in[4];
    const int* t2    = (const int*)d_in[5];
    const int* p2    = (const int*)d_in[6];
    float* out = (float*)d_out;

    static bool attr_set = false;
    if (!attr_set) {
        cudaFuncSetAttribute(gemm_lse_kernel,
                             cudaFuncAttributeMaxDynamicSharedMemorySize, GEMM_SMEM);
        attr_set = true;
    }

    prep_kernel<<<WCONV_BLOCKS + B_SZ, 256>>>(w, x);
    gemm_lse_kernel<<<dim3(4, NCHB), 256, GEMM_SMEM>>>();
    row_kernel<<<B_SZ, 256>>>(lam, t1, p1, t2, p2, out);
}

// round 8
// speedup vs baseline: 1.2275x; 1.0945x over previous
#include <cuda_runtime.h>
#include <cuda_fp16.h>
#include <cstdint>

// ---------------- problem constants ----------------
#define B_SZ 512
#define D_SZ 256
#define C_SZ 100000
#define C_PAD 100096              // 782 * 128
#define NCHB 782                  // class chunks of 128
#define MARGIN 0.2f
#define SCALE  30.0f
#define SHIFT  30.0f              // fixed LSE shift: logits <= S = 30
#define WCONV_BLOCKS 6250         // 16 classes per block (2 per warp)

// GEMM smem: 4 stages x (A 8KB + B 8KB) = 64KB, + 1KB reduce buffer
#define STAGE_BYTES 16384
#define RBUF_OFF    65536
#define GEMM_SMEM   (65536 + 1024)

// ---------------- device scratch (no runtime alloc) ----------------
__device__ __align__(16) __half g_wh[(size_t)C_PAD * D_SZ];  // l2norm(W) fp16; pad rows zero
__device__ __align__(16) __half g_xh[B_SZ * D_SZ];           // S * l2norm(x) fp16
__device__ float g_psum[(size_t)B_SZ * NCHB];   // per-(row, chunk) sum of exp(v - SHIFT)
__device__ float g_loss[B_SZ];
__device__ unsigned g_cnt;

// ---------------- PTX helpers ----------------
__device__ __forceinline__ uint32_t smem_u32(const void* p) {
    uint32_t a;
    asm("{ .reg .u64 t; cvta.to.shared.u64 t, %1; cvt.u32.u64 %0, t; }" : "=r"(a) : "l"(p));
    return a;
}
#define CP_ASYNC16(dst, src) \
    asm volatile("cp.async.cg.shared.global [%0], [%1], 16;" :: "r"(dst), "l"(src) : "memory")
#define CP_COMMIT() asm volatile("cp.async.commit_group;" ::: "memory")
#define CP_WAIT(n)  asm volatile("cp.async.wait_group %0;" :: "n"(n) : "memory")

#define LDSM_X4(r0, r1, r2, r3, addr) \
    asm volatile("ldmatrix.sync.aligned.m8n8.x4.shared.b16 {%0,%1,%2,%3}, [%4];" \
        : "=r"(r0), "=r"(r1), "=r"(r2), "=r"(r3) : "r"(addr))

// fp16 in, fp16 accumulate: D(2x f16x2) = A(4) * B(2) + D
#define MMA_F16ACC(d0, d1, a0, a1, a2, a3, b0, b1) \
    asm volatile("mma.sync.aligned.m16n8k16.row.col.f16.f16.f16.f16 " \
        "{%0,%1}, {%2,%3,%4,%5}, {%6,%7}, {%0,%1};" \
        : "+r"(d0), "+r"(d1) \
        : "r"(a0), "r"(a1), "r"(a2), "r"(a3), "r"(b0), "r"(b1))

// ---------------- kernel 1: fused prep ----------------
__global__ void prep_kernel(const float* __restrict__ w, const float* __restrict__ x) {
    if (blockIdx.x < WCONV_BLOCKS) {
        int cls0 = blockIdx.x * 16 + (threadIdx.x >> 5) * 2;
        int lane = threadIdx.x & 31;
        const float4* w0r = (const float4*)(w + (size_t)cls0 * D_SZ);
        const float4* w1r = (const float4*)(w + (size_t)(cls0 + 1) * D_SZ);
        float4 a0 = w0r[lane], a1 = w0r[lane + 32];
        float4 b0 = w1r[lane], b1 = w1r[lane + 32];
        float sa = a0.x*a0.x + a0.y*a0.y + a0.z*a0.z + a0.w*a0.w
                 + a1.x*a1.x + a1.y*a1.y + a1.z*a1.z + a1.w*a1.w;
        float sb = b0.x*b0.x + b0.y*b0.y + b0.z*b0.z + b0.w*b0.w
                 + b1.x*b1.x + b1.y*b1.y + b1.z*b1.z + b1.w*b1.w;
        #pragma unroll
        for (int m = 16; m; m >>= 1) {
            sa += __shfl_xor_sync(0xffffffffu, sa, m);
            sb += __shfl_xor_sync(0xffffffffu, sb, m);
        }
        float ia = 1.0f / fmaxf(sqrtf(sa), 1e-12f);
        float ib = 1.0f / fmaxf(sqrtf(sb), 1e-12f);
        __half2* o0 = (__half2*)(g_wh + (size_t)cls0 * D_SZ);
        __half2* o1 = (__half2*)(g_wh + (size_t)(cls0 + 1) * D_SZ);
        o0[2*lane]        = __floats2half2_rn(a0.x * ia, a0.y * ia);
        o0[2*lane + 1]    = __floats2half2_rn(a0.z * ia, a0.w * ia);
        o0[64 + 2*lane]   = __floats2half2_rn(a1.x * ia, a1.y * ia);
        o0[64 + 2*lane+1] = __floats2half2_rn(a1.z * ia, a1.w * ia);
        o1[2*lane]        = __floats2half2_rn(b0.x * ib, b0.y * ib);
        o1[2*lane + 1]    = __floats2half2_rn(b0.z * ib, b0.w * ib);
        o1[64 + 2*lane]   = __floats2half2_rn(b1.x * ib, b1.y * ib);
        o1[64 + 2*lane+1] = __floats2half2_rn(b1.z * ib, b1.w * ib);
    } else {
        int b = blockIdx.x - WCONV_BLOCKS, t = threadIdx.x;   // 256 threads
        if (b == 0 && t == 0) g_cnt = 0;
        float v = x[b * D_SZ + t];
        float s = v * v;
        #pragma unroll
        for (int m = 16; m; m >>= 1) s += __shfl_xor_sync(0xffffffffu, s, m);
        __shared__ float ws[8];
        if ((t & 31) == 0) ws[t >> 5] = s;
        __syncthreads();
        __shared__ float inv;
        if (t == 0) {
            float tot = 0.f;
            #pragma unroll
            for (int i = 0; i < 8; i++) tot += ws[i];
            inv = 1.0f / fmaxf(sqrtf(tot), 1e-12f);
        }
        __syncthreads();
        g_xh[b * D_SZ + t] = __float2half_rn(SCALE * v * inv);
    }
}

// ---------------- kernel 2: fp16 HMMA GEMM, 64x64 warp tiles ----------------
// grid (4, 782). 128 threads = 4 warps (2m x 2n), warp tile 64m x 64n.
__global__ void __launch_bounds__(128, 3)
gemm_lse_kernel() {
    extern __shared__ __align__(1024) char smem[];
    const uint32_t sb = smem_u32(smem);
    const int tid = threadIdx.x, lane = tid & 31, wid = tid >> 5;
    const int wm = wid >> 1, wn = wid & 1;            // warp grid 2 x 2
    const int chunk = blockIdx.y, c0 = chunk * 128, b0 = blockIdx.x * 128;

    // ---- cp.async producer: 4 A-chunks + 4 B-chunks of 16B per thread ----
    uint32_t swz[4];
    const __half *gA[4], *gB[4];
    #pragma unroll
    for (int i = 0; i < 4; i++) {
        int f = tid + 128 * i;                // 16B chunk id in 128x32 tile
        int row = f >> 2, c16 = f & 3;
        swz[i] = (uint32_t)row * 64 + ((uint32_t)(c16 ^ ((row >> 1) & 3)) << 4);
        gA[i] = g_xh + (size_t)(b0 + row) * D_SZ + c16 * 8;
        gB[i] = g_wh + (size_t)(c0 + row) * D_SZ + c16 * 8;
    }

    auto load_stage = [&](int kt) {
        uint32_t abase = sb + (kt & 3) * STAGE_BYTES;
        uint32_t bbase = abase + 8192;
        #pragma unroll
        for (int i = 0; i < 4; i++) CP_ASYNC16(abase + swz[i], gA[i] + kt * 32);
        #pragma unroll
        for (int i = 0; i < 4; i++) CP_ASYNC16(bbase + swz[i], gB[i] + kt * 32);
        CP_COMMIT();
    };

    // ---- ldmatrix consumer indexing ----
    const int rA = wm * 64 + (lane & 15);
    const uint32_t aoff = (uint32_t)rA * 64;
    const int saN = (rA >> 1) & 3;
    const int cA = lane >> 4;
    const int rB = wn * 64 + ((lane >> 4) << 3) + (lane & 7);
    const uint32_t boff = (uint32_t)rB * 64;
    const int sbN = (rB >> 1) & 3;
    const int cB = (lane >> 3) & 1;

    uint32_t acc[4][8][2];                 // f16x2 accumulators, 64 regs
    #pragma unroll
    for (int i = 0; i < 4; i++)
        #pragma unroll
        for (int j = 0; j < 8; j++) { acc[i][j][0] = 0u; acc[i][j][1] = 0u; }

    auto compute_stage = [&](int st) {
        uint32_t aBase = sb + st * STAGE_BYTES;
        uint32_t bBase = aBase + 8192;
        #pragma unroll
        for (int s = 0; s < 2; s++) {                 // two k16 steps per BK=32
            uint32_t a_[4][4], b_[4][4];
            #pragma unroll
            for (int mt = 0; mt < 4; mt++) {
                uint32_t ad = aBase + aoff + mt * 1024 +
                              ((uint32_t)((s * 2 + cA) ^ saN) << 4);
                LDSM_X4(a_[mt][0], a_[mt][1], a_[mt][2], a_[mt][3], ad);
            }
            #pragma unroll
            for (int jp = 0; jp < 4; jp++) {
                uint32_t bd = bBase + boff + jp * 1024 +
                              ((uint32_t)((s * 2 + cB) ^ sbN) << 4);
                LDSM_X4(b_[jp][0], b_[jp][1], b_[jp][2], b_[jp][3], bd);
            }
            #pragma unroll
            for (int mt = 0; mt < 4; mt++)
                #pragma unroll
                for (int nt = 0; nt < 8; nt++) {
                    int jp = nt >> 1, hb = (nt & 1) * 2;
                    MMA_F16ACC(acc[mt][nt][0], acc[mt][nt][1],
                               a_[mt][0], a_[mt][1], a_[mt][2], a_[mt][3],
                               b_[jp][hb], b_[jp][hb + 1]);
                }
        }
    };

    // ---- pipeline: 8 K-stages, 4 buffers, 3 in flight ----
    load_stage(0); load_stage(1); load_stage(2);
    #pragma unroll 1
    for (int kt = 0; kt < 5; kt++) {
        CP_WAIT(2); __syncthreads();
        compute_stage(kt & 3);
        load_stage(kt + 3);
    }
    CP_WAIT(2); __syncthreads(); compute_stage(1);
    CP_WAIT(1); __syncthreads(); compute_stage(2);
    CP_WAIT(0); __syncthreads(); compute_stage(3);

    // ---- epilogue: per-row sum of exp(v - SHIFT) ----
    const bool edge = (c0 + 128 > C_SZ);
    float es[4][2];
    #pragma unroll
    for (int mt = 0; mt < 4; mt++) { es[mt][0] = 0.f; es[mt][1] = 0.f; }
    #pragma unroll
    for (int mt = 0; mt < 4; mt++)
        #pragma unroll
        for (int nt = 0; nt < 8; nt++) {
            int cgb = c0 + wn * 64 + nt * 8 + (lane & 3) * 2;
            #pragma unroll
            for (int h = 0; h < 2; h++) {
                float2 v = __half22float2(*(__half2*)&acc[mt][nt][h]);
                float t0 = __expf(v.x - SHIFT);
                float t1 = __expf(v.y - SHIFT);
                if (edge && (cgb + 0 >= C_SZ)) t0 = 0.f;
                if (edge && (cgb + 1 >= C_SZ)) t1 = 0.f;
                es[mt][h] += t0 + t1;
            }
        }
    #pragma unroll
    for (int m = 1; m <= 2; m <<= 1)
        #pragma unroll
        for (int mt = 0; mt < 4; mt++) {
            es[mt][0] += __shfl_xor_sync(0xffffffffu, es[mt][0], m);
            es[mt][1] += __shfl_xor_sync(0xffffffffu, es[mt][1], m);
        }

    float* rbuf = (float*)(smem + RBUF_OFF);          // [2 wm][2 wn][64 rows]
    if ((lane & 3) == 0) {
        int rl = lane >> 2;
        #pragma unroll
        for (int mt = 0; mt < 4; mt++) {
            rbuf[(wm * 2 + wn) * 64 + mt * 16 + rl]     = es[mt][0];
            rbuf[(wm * 2 + wn) * 64 + mt * 16 + 8 + rl] = es[mt][1];
        }
    }
    __syncthreads();
    {
        int wmx = tid >> 6, rl = tid & 63;
        float s = rbuf[(wmx * 2 + 0) * 64 + rl] + rbuf[(wmx * 2 + 1) * 64 + rl];
        g_psum[(size_t)(b0 + tid) * NCHB + chunk] = s;
    }
}

// ---------------- kernel 3: per-row specials + LSE merge + loss + fused final ----------------
__global__ void row_kernel(const float* __restrict__ lamp,
                           const int* __restrict__ t1, const int* __restrict__ p1,
                           const int* __restrict__ t2, const int* __restrict__ p2,
                           float* __restrict__ out) {
    int b = blockIdx.x;
    int tid = threadIdx.x, wid = tid >> 5, lane = tid & 31;

    __shared__ float sv[4], svraw[4];
    __shared__ int   sidx[4];
    __shared__ float ss[256];
    __shared__ bool  lastb;

    int i0 = t1[b], i1 = p1[b], i2 = t2[b], i3 = p2[b];

    if (wid < 4) {
        int qi = (wid == 0) ? i0 : (wid == 1) ? i1 : (wid == 2) ? i2 : i3;
        const uint4* xr = (const uint4*)(g_xh + (size_t)b * D_SZ);
        const uint4* wr = (const uint4*)(g_wh + (size_t)qi * D_SZ);
        uint4 xv = xr[lane], wv = wr[lane];   // 8 fp16 each
        float s = 0.f;
        const uint32_t* xu = (const uint32_t*)&xv;
        const uint32_t* wu = (const uint32_t*)&wv;
        #pragma unroll
        for (int i = 0; i < 4; i++) {
            float2 xf = __half22float2(*(const __half2*)&xu[i]);
            float2 wf = __half22float2(*(const __half2*)&wu[i]);
            s += xf.x * wf.x + xf.y * wf.y;
        }
        #pragma unroll
        for (int m = 16; m; m >>= 1) s += __shfl_xor_sync(0xffffffffu, s, m);
        if (lane == 0) {
            float raw = s;                               // ~= what the GEMM summed
            float val = raw;
            if (qi == i0) val = raw - SCALE * MARGIN;    // pre-scale scatter
            if (qi == i1) val = raw / SCALE - MARGIN;    // post-scale scatters
            if (qi == i2) val = raw / SCALE - MARGIN;
            if (qi == i3) val = raw / SCALE - MARGIN;    // last write wins
            svraw[wid] = raw;
            sv[wid] = val;
            sidx[wid] = qi;
        }
    }

    float s = 0.f;
    for (int i = tid; i < NCHB; i += 256) s += g_psum[(size_t)b * NCHB + i];
    ss[tid] = s;
    __syncthreads();
    for (int st = 128; st; st >>= 1) {
        if (tid < st) ss[tid] += ss[tid + st];
        __syncthreads();
    }

    if (tid == 0) {
        float S0 = ss[0];
        #pragma unroll
        for (int q = 0; q < 3; q++) {
            bool lastq = true;
            #pragma unroll
            for (int r = q + 1; r < 4; r++) if (sidx[r] == sidx[q]) lastq = false;
            if (lastq) S0 += __expf(sv[q] - SHIFT) - __expf(svraw[q] - SHIFT);
        }
        S0 += __expf(sv[3] - SHIFT) - __expf(svraw[3] - SHIFT);
        float lz = SHIFT + logf(S0);
        float lam = *lamp;
        g_loss[b] = lam * (0.2f * (lz - sv[0]) + 0.8f * (lz - sv[1]))
                  + (1.f - lam) * (0.2f * (lz - sv[2]) + 0.8f * (lz - sv[3]));
        __threadfence();
        lastb = (atomicAdd(&g_cnt, 1u) == B_SZ - 1);
    }
    __syncthreads();

    if (lastb) {
        float r = 0.f;
        for (int i = tid; i < B_SZ; i += 256) r += __ldcg(&g_loss[i]);
        ss[tid] = r;
        __syncthreads();
        for (int st = 128; st; st >>= 1) {
            if (tid < st) ss[tid] += ss[tid + st];
            __syncthreads();
        }
        if (tid == 0) out[0] = ss[0] / (float)B_SZ;
    }
}

// ---------------- host launch ----------------
extern "C" void kernel_launch(void* const* d_in, const int* in_sizes, int n_in,
                              void* d_out, int out_size) {
    const float* x   = (const float*)d_in[0];
    const float* w   = (const float*)d_in[1];
    const float* lam = (const float*)d_in[2];
    const int* t1    = (const int*)d_in[3];
    const int* p1    = (const int*)d_in[4];
    const int* t2    = (const int*)d_in[5];
    const int* p2    = (const int*)d_in[6];
    float* out = (float*)d_out;

    static bool attr_set = false;
    if (!attr_set) {
        cudaFuncSetAttribute(gemm_lse_kernel,
                             cudaFuncAttributeMaxDynamicSharedMemorySize, GEMM_SMEM);
        attr_set = true;
    }

    prep_kernel<<<WCONV_BLOCKS + B_SZ, 256>>>(w, x);
    gemm_lse_kernel<<<dim3(4, NCHB), 128, GEMM_SMEM>>>();
    row_kernel<<<B_SZ, 256>>>(lam, t1, p1, t2, p2, out);
}